// round 16
// baseline (speedup 1.0000x reference)
#include <cuda_runtime.h>
#include <stdint.h>

// Binarized depthwise 3x3 conv, stride 1, SAME. x:(16,112,112,256) NHWC fp32,
// kernel:(3,3,256,1). out = sum over valid taps of sign(x)*sign(k).
//
// bf16x2 math (exact, |sum|<=9): carrier = PRMT of two fp32 high halves;
// tap = (carrier & 0x80008000) ^ kp (kp = bf16x2 +-1.0; 0 for missing border
// rows -> +-0.0 no-op under add.rn.bf16x2). Column recurrence:
//   out[c-1] = A + q2(c); A = B + q1(c); B = q0(c)
//
// Warp-private cp.async pipeline, two-column stages. This round: D=3 slots
// (24KB smem) + launch_bounds(128,8) -> 8 CTAs/SM (was 6), trading pipeline
// depth (still 2 stages = 16KB in flight/CTA) for occupancy.

#define NN 16
#define HH 112
#define WW 112
#define CC 256
#define RS (WW * CC)
#define D  3                     // slots; each slot = 2 columns (2KB/warp)

__device__ __forceinline__ uint32_t badd(uint32_t a, uint32_t b) {
    uint32_t r;
    asm("add.rn.bf16x2 %0, %1, %2;" : "=r"(r) : "r"(a), "r"(b));
    return r;
}

#define TAPP(t, kp) ((((t) & 0x80008000u)) ^ (kp))

__device__ __forceinline__ void carr(const uint4 v, uint32_t& a, uint32_t& b) {
    a = __byte_perm(v.x, v.y, 0x7632);
    b = __byte_perm(v.z, v.w, 0x7632);
}

__device__ __forceinline__ void store4(float* __restrict__ p,
                                       uint32_t oa, uint32_t ob) {
    float4 o4;
    o4.x = __uint_as_float(oa << 16);
    o4.y = __uint_as_float(oa & 0xFFFF0000u);
    o4.z = __uint_as_float(ob << 16);
    o4.w = __uint_as_float(ob & 0xFFFF0000u);
    *reinterpret_cast<float4*>(p) = o4;
}

// Compute q0..q2 (both halves) for smem column (slotv, col2v).
#define COLQ(slotv, col2v)                                                                              \
    {                                                                                                   \
        uint32_t t0a, t0b, t1a, t1b, t2a, t2b;                                                          \
        carr(stage[w][slotv][col2v][rr][ql],     t0a, t0b);                                             \
        carr(stage[w][slotv][col2v][rr + 1][ql], t1a, t1b);                                             \
        carr(stage[w][slotv][col2v][rr + 2][ql], t2a, t2b);                                             \
        q0a = badd(badd(TAPP(t0a, kp[0][0][0]), TAPP(t1a, kp[1][0][0])), TAPP(t2a, kp[2][0][0]));        \
        q0b = badd(badd(TAPP(t0b, kp[0][0][1]), TAPP(t1b, kp[1][0][1])), TAPP(t2b, kp[2][0][1]));        \
        q1a = badd(badd(TAPP(t0a, kp[0][1][0]), TAPP(t1a, kp[1][1][0])), TAPP(t2a, kp[2][1][0]));        \
        q1b = badd(badd(TAPP(t0b, kp[0][1][1]), TAPP(t1b, kp[1][1][1])), TAPP(t2b, kp[2][1][1]));        \
        q2a = badd(badd(TAPP(t0a, kp[0][2][0]), TAPP(t1a, kp[1][2][0])), TAPP(t2a, kp[2][2][0]));        \
        q2b = badd(badd(TAPP(t0b, kp[0][2][1]), TAPP(t1b, kp[1][2][1])), TAPP(t2b, kp[2][2][1]));        \
    }

// Load 2-column pair `pairIdx` into slot `slotIdx` (4 cp.async per thread).
#define LOADPAIR(slotIdx, pairIdx)                                                                      \
    {                                                                                                   \
        const int cA = cbeg + 2 * (pairIdx);                                                            \
        const uint32_t dd = myd + (uint32_t)(slotIdx) * 2048u;                                          \
        asm volatile("cp.async.cg.shared.global [%0], [%1], 16;"                                        \
                     :: "r"(dd), "l"(L0 + (size_t)cA * CC) : "memory");                                 \
        asm volatile("cp.async.cg.shared.global [%0], [%1], 16;"                                        \
                     :: "r"(dd + 256u), "l"(L1 + (size_t)cA * CC) : "memory");                          \
        asm volatile("cp.async.cg.shared.global [%0], [%1], 16;"                                        \
                     :: "r"(dd + 1024u), "l"(L0 + (size_t)(cA + 1) * CC) : "memory");                   \
        asm volatile("cp.async.cg.shared.global [%0], [%1], 16;"                                        \
                     :: "r"(dd + 1280u), "l"(L1 + (size_t)(cA + 1) * CC) : "memory");                   \
    }

__global__ __launch_bounds__(128, 8)
void bconv_kernel(const float* __restrict__ x,
                  const float* __restrict__ k,
                  float* __restrict__ out) {
    // [warp][slot][col2][band row][quad]; warp-private slices. 24KB.
    __shared__ uint4 stage[4][D][2][4][16];

    const int hpair = blockIdx.x >> 1;   // 0..55
    const int strip = blockIdx.x & 1;    // two 56-col strips
    const int n = blockIdx.y;
    const int t = threadIdx.x;
    const int w = t >> 5;                // warp: 64-channel group
    const int lid = t & 31;
    const int ql = lid & 15;             // quad within warp
    const int rr = lid >> 4;             // output row within pair (0/1)

    const int h0 = hpair * 2;
    const int h = h0 + rr;               // my output row
    const int c0 = (w * 16 + ql) * 4;    // first channel of my quad

    // Kernel signs for MY output row; zero outer taps at image borders.
    const bool zt = (h == 0);
    const bool zb = (h == HH - 1);
    uint32_t kp[3][3][2];
#pragma unroll
    for (int kh = 0; kh < 3; ++kh) {
        const bool zz = (kh == 0 && zt) || (kh == 2 && zb);
#pragma unroll
        for (int kw = 0; kw < 3; ++kw) {
            const float4 kv = *reinterpret_cast<const float4*>(k + (kh * 3 + kw) * CC + c0);
            uint32_t s0 = (kv.x >= 0.0f) ? 0x3F80u : 0xBF80u;
            uint32_t s1 = (kv.y >= 0.0f) ? 0x3F80u : 0xBF80u;
            uint32_t s2 = (kv.z >= 0.0f) ? 0x3F80u : 0xBF80u;
            uint32_t s3 = (kv.w >= 0.0f) ? 0x3F80u : 0xBF80u;
            kp[kh][kw][0] = zz ? 0u : (s0 | (s1 << 16));
            kp[kh][kw][1] = zz ? 0u : (s2 | (s3 << 16));
        }
    }

    // Loader role: thread loads band rows 2rr, 2rr+1 (band = h0-1..h0+2,
    // clamped; clamped rows' contributions are zeroed via kp).
    int lr0 = h0 - 1 + 2 * rr; if (lr0 < 0) lr0 = 0;
    int lr1 = h0 + 2 * rr;     if (lr1 > HH - 1) lr1 = HH - 1;
    const float* L0 = x + ((size_t)n * HH + lr0) * RS + c0;
    const float* L1 = x + ((size_t)n * HH + lr1) * RS + c0;
    float*       o  = out + ((size_t)n * HH + h) * RS + c0;

    const int ws = strip * 56;
    const int we = ws + 56;
    const int cbeg = (ws == 0) ? 0 : ws - 1;
    const int cend = (we == WW) ? WW - 1 : we;   // 57th (tail) column
    const int sfirst = ws + 1;           // first column whose iter stores

    // SMEM byte address of my (slot0, col0, row 2rr, quad) cell.
    const uint32_t sbase = (uint32_t)__cvta_generic_to_shared(&stage[w][0][0][0][0]);
    const uint32_t myd = sbase + ((2 * rr) * 16 + ql) * 16;

    // ---- prologue: pairs 0..D-2 into slots 0..D-2 ----
#pragma unroll
    for (int p = 0; p < D - 1; ++p) {
        LOADPAIR(p, p);
        asm volatile("cp.async.commit_group;" ::: "memory");
    }

    uint32_t Aa, Ab, Ba, Bb;
    uint32_t q0a, q0b, q1a, q1b, q2a, q2b;

    // ---- peeled pair 0 (slot 0; cols cbeg, cbeg+1) ----
    asm volatile("cp.async.wait_group %0;" :: "n"(D - 2) : "memory");
    __syncwarp();
    COLQ(0, 0);                           // c = cbeg: init only
    Aa = q1a; Ab = q1b; Ba = q0a; Bb = q0b;
    COLQ(0, 1);                           // c = cbeg+1
    if (cbeg + 1 >= sfirst)               // uniform (strip 0 stores out[0])
        store4(o + (size_t)cbeg * CC, badd(Aa, q2a), badd(Ab, q2b));
    Aa = badd(Ba, q1a); Ba = q0a;
    Ab = badd(Bb, q1b); Bb = q0b;
    LOADPAIR(D - 1, D - 1);               // pair D-1 -> slot D-1
    asm volatile("cp.async.commit_group;" ::: "memory");

    // ---- main loop: pairs 1..27 (slot = p % D; always store) ----
    int slot = 1;
    for (int p = 1; p < 28; ++p) {
        asm volatile("cp.async.wait_group %0;" :: "n"(D - 2) : "memory");
        __syncwarp();
        const int c1 = cbeg + 2 * p;

        COLQ(slot, 0);                    // col c1: stores out[c1-1]
        store4(o + (size_t)(c1 - 1) * CC, badd(Aa, q2a), badd(Ab, q2b));
        Aa = badd(Ba, q1a); Ba = q0a;
        Ab = badd(Bb, q1b); Bb = q0b;

        COLQ(slot, 1);                    // col c1+1: stores out[c1]
        store4(o + (size_t)c1 * CC, badd(Aa, q2a), badd(Ab, q2b));
        Aa = badd(Ba, q1a); Ba = q0a;
        Ab = badd(Bb, q1b); Bb = q0b;

        // Refill pair p+D-1 -> slot (p+D-1)%D == the slot read LAST
        // iteration (race-safe behind this iteration's syncwarp).
        if (p + D - 1 < 28) {             // uniform
            int rslot = slot - 1; if (rslot < 0) rslot = D - 1;
            LOADPAIR(rslot, p + D - 1);
        }
        asm volatile("cp.async.commit_group;" ::: "memory");  // uniform counts
        slot = (slot + 1 == D) ? 0 : slot + 1;
    }

    // ---- tail column cend (direct LDG). Band rows for MY output row are
    // derivable from L0/L1 with +-RS offsets (no new pointers):
    //  rr=0: rows (h-1, h, h+1) = (L0 clamped, L1, L1+RS)
    //  rr=1: rows (h-1, h, h+1) = (L0-RS, L0, L1 clamped)
    {
        const float* R0 = rr ? L0 - RS : L0;
        const float* R1 = rr ? L0      : L1;
        const float* R2 = rr ? L1      : L1 + RS;
        uint32_t t0a, t0b, t1a, t1b, t2a, t2b;
        carr(*reinterpret_cast<const uint4*>(R0 + (size_t)cend * CC), t0a, t0b);
        carr(*reinterpret_cast<const uint4*>(R1 + (size_t)cend * CC), t1a, t1b);
        carr(*reinterpret_cast<const uint4*>(R2 + (size_t)cend * CC), t2a, t2b);
        q1a = badd(badd(TAPP(t0a, kp[0][1][0]), TAPP(t1a, kp[1][1][0])), TAPP(t2a, kp[2][1][0]));
        q1b = badd(badd(TAPP(t0b, kp[0][1][1]), TAPP(t1b, kp[1][1][1])), TAPP(t2b, kp[2][1][1]));
        q2a = badd(badd(TAPP(t0a, kp[0][2][0]), TAPP(t1a, kp[1][2][0])), TAPP(t2a, kp[2][2][0]));
        q2b = badd(badd(TAPP(t0b, kp[0][2][1]), TAPP(t1b, kp[1][2][1])), TAPP(t2b, kp[2][2][1]));
        store4(o + (size_t)(cend - 1) * CC, badd(Aa, q2a), badd(Ab, q2b));
        Aa = badd(Ba, q1a);
        Ab = badd(Bb, q1b);
    }

    if (we == WW)  // right edge: out[111] = q0(110) + q1(111) = A
        store4(o + (size_t)(WW - 1) * CC, Aa, Ab);
}

extern "C" void kernel_launch(void* const* d_in, const int* in_sizes, int n_in,
                              void* d_out, int out_size) {
    const float* x = (const float*)d_in[0];
    const float* k = (const float*)d_in[1];
    float* out = (float*)d_out;
    dim3 grid(112, NN);   // 56 row-pairs x 2 strips
    bconv_kernel<<<grid, 128>>>(x, k, out);
}

// round 17
// speedup vs baseline: 1.0310x; 1.0310x over previous
#include <cuda_runtime.h>
#include <stdint.h>

// Binarized depthwise 3x3 conv, stride 1, SAME. x:(16,112,112,256) NHWC fp32,
// kernel:(3,3,256,1). out = sum over valid taps of sign(x)*sign(k).
//
// bf16x2 math (exact, |sum|<=9): carrier = PRMT of two fp32 high halves;
// tap = (carrier & 0x80008000) ^ kp (kp = bf16x2 +-1.0; 0 for missing border
// rows -> +-0.0 no-op under add.rn.bf16x2). Column recurrence:
//   out[c-1] = A + q2(c); A = B + q1(c); B = q0(c)
//
// Warp-private cp.async pipeline, two-column stages, D=4 slots (R15 config —
// proven best). This round: refill issued at TOP of each iteration (slot was
// read last iteration; syncwarp orders those reads before the new writes),
// and the pair loop is unrolled 4x so slot indices fold to immediates.

#define NN 16
#define HH 112
#define WW 112
#define CC 256
#define RS (WW * CC)
#define D  4                     // slots; each slot = 2 columns (2KB/warp)

__device__ __forceinline__ uint32_t badd(uint32_t a, uint32_t b) {
    uint32_t r;
    asm("add.rn.bf16x2 %0, %1, %2;" : "=r"(r) : "r"(a), "r"(b));
    return r;
}

#define TAPP(t, kp) ((((t) & 0x80008000u)) ^ (kp))

__device__ __forceinline__ void carr(const uint4 v, uint32_t& a, uint32_t& b) {
    a = __byte_perm(v.x, v.y, 0x7632);
    b = __byte_perm(v.z, v.w, 0x7632);
}

__device__ __forceinline__ void store4(float* __restrict__ p,
                                       uint32_t oa, uint32_t ob) {
    float4 o4;
    o4.x = __uint_as_float(oa << 16);
    o4.y = __uint_as_float(oa & 0xFFFF0000u);
    o4.z = __uint_as_float(ob << 16);
    o4.w = __uint_as_float(ob & 0xFFFF0000u);
    *reinterpret_cast<float4*>(p) = o4;
}

// Compute q0..q2 (both halves) for smem column (slotv, col2v).
#define COLQ(slotv, col2v)                                                                              \
    {                                                                                                   \
        uint32_t t0a, t0b, t1a, t1b, t2a, t2b;                                                          \
        carr(stage[w][slotv][col2v][rr][ql],     t0a, t0b);                                             \
        carr(stage[w][slotv][col2v][rr + 1][ql], t1a, t1b);                                             \
        carr(stage[w][slotv][col2v][rr + 2][ql], t2a, t2b);                                             \
        q0a = badd(badd(TAPP(t0a, kp[0][0][0]), TAPP(t1a, kp[1][0][0])), TAPP(t2a, kp[2][0][0]));        \
        q0b = badd(badd(TAPP(t0b, kp[0][0][1]), TAPP(t1b, kp[1][0][1])), TAPP(t2b, kp[2][0][1]));        \
        q1a = badd(badd(TAPP(t0a, kp[0][1][0]), TAPP(t1a, kp[1][1][0])), TAPP(t2a, kp[2][1][0]));        \
        q1b = badd(badd(TAPP(t0b, kp[0][1][1]), TAPP(t1b, kp[1][1][1])), TAPP(t2b, kp[2][1][1]));        \
        q2a = badd(badd(TAPP(t0a, kp[0][2][0]), TAPP(t1a, kp[1][2][0])), TAPP(t2a, kp[2][2][0]));        \
        q2b = badd(badd(TAPP(t0b, kp[0][2][1]), TAPP(t1b, kp[1][2][1])), TAPP(t2b, kp[2][2][1]));        \
    }

// Load 2-column pair `pairIdx` into slot `slotIdx` (4 cp.async per thread).
#define LOADPAIR(slotIdx, pairIdx)                                                                      \
    {                                                                                                   \
        const int cA = cbeg + 2 * (pairIdx);                                                            \
        const uint32_t dd = myd + (uint32_t)(slotIdx) * 2048u;                                          \
        asm volatile("cp.async.cg.shared.global [%0], [%1], 16;"                                        \
                     :: "r"(dd), "l"(L0 + (size_t)cA * CC) : "memory");                                 \
        asm volatile("cp.async.cg.shared.global [%0], [%1], 16;"                                        \
                     :: "r"(dd + 256u), "l"(L1 + (size_t)cA * CC) : "memory");                          \
        asm volatile("cp.async.cg.shared.global [%0], [%1], 16;"                                        \
                     :: "r"(dd + 1024u), "l"(L0 + (size_t)(cA + 1) * CC) : "memory");                   \
        asm volatile("cp.async.cg.shared.global [%0], [%1], 16;"                                        \
                     :: "r"(dd + 1280u), "l"(L1 + (size_t)(cA + 1) * CC) : "memory");                   \
    }

__global__ __launch_bounds__(128, 6)
void bconv_kernel(const float* __restrict__ x,
                  const float* __restrict__ k,
                  float* __restrict__ out) {
    // [warp][slot][col2][band row][quad]; warp-private slices. 32KB.
    __shared__ uint4 stage[4][D][2][4][16];

    const int hpair = blockIdx.x >> 1;   // 0..55
    const int strip = blockIdx.x & 1;    // two 56-col strips
    const int n = blockIdx.y;
    const int t = threadIdx.x;
    const int w = t >> 5;                // warp: 64-channel group
    const int lid = t & 31;
    const int ql = lid & 15;             // quad within warp
    const int rr = lid >> 4;             // output row within pair (0/1)

    const int h0 = hpair * 2;
    const int h = h0 + rr;               // my output row
    const int c0 = (w * 16 + ql) * 4;    // first channel of my quad

    // Kernel signs for MY output row; zero outer taps at image borders.
    const bool zt = (h == 0);
    const bool zb = (h == HH - 1);
    uint32_t kp[3][3][2];
#pragma unroll
    for (int kh = 0; kh < 3; ++kh) {
        const bool zz = (kh == 0 && zt) || (kh == 2 && zb);
#pragma unroll
        for (int kw = 0; kw < 3; ++kw) {
            const float4 kv = *reinterpret_cast<const float4*>(k + (kh * 3 + kw) * CC + c0);
            uint32_t s0 = (kv.x >= 0.0f) ? 0x3F80u : 0xBF80u;
            uint32_t s1 = (kv.y >= 0.0f) ? 0x3F80u : 0xBF80u;
            uint32_t s2 = (kv.z >= 0.0f) ? 0x3F80u : 0xBF80u;
            uint32_t s3 = (kv.w >= 0.0f) ? 0x3F80u : 0xBF80u;
            kp[kh][kw][0] = zz ? 0u : (s0 | (s1 << 16));
            kp[kh][kw][1] = zz ? 0u : (s2 | (s3 << 16));
        }
    }

    // Loader role: thread loads band rows 2rr, 2rr+1 (band = h0-1..h0+2,
    // clamped; clamped rows' contributions are zeroed via kp).
    int lr0 = h0 - 1 + 2 * rr; if (lr0 < 0) lr0 = 0;
    int lr1 = h0 + 2 * rr;     if (lr1 > HH - 1) lr1 = HH - 1;
    const float* L0 = x + ((size_t)n * HH + lr0) * RS + c0;
    const float* L1 = x + ((size_t)n * HH + lr1) * RS + c0;
    float*       o  = out + ((size_t)n * HH + h) * RS + c0;

    const int ws = strip * 56;
    const int we = ws + 56;
    const int cbeg = (ws == 0) ? 0 : ws - 1;
    const int cend = (we == WW) ? WW - 1 : we;   // 57th (tail) column
    const int sfirst = ws + 1;           // first column whose iter stores

    // SMEM byte address of my (slot0, col0, row 2rr, quad) cell.
    const uint32_t sbase = (uint32_t)__cvta_generic_to_shared(&stage[w][0][0][0][0]);
    const uint32_t myd = sbase + ((2 * rr) * 16 + ql) * 16;

    // ---- prologue: pairs 0..D-2 into slots 0..D-2 ----
#pragma unroll
    for (int p = 0; p < D - 1; ++p) {
        LOADPAIR(p, p);
        asm volatile("cp.async.commit_group;" ::: "memory");
    }

    uint32_t Aa, Ab, Ba, Bb;
    uint32_t q0a, q0b, q1a, q1b, q2a, q2b;

    // ---- peeled pair 0 (slot 0; cols cbeg, cbeg+1) ----
    asm volatile("cp.async.wait_group %0;" :: "n"(D - 2) : "memory");
    __syncwarp();
    LOADPAIR(D - 1, D - 1);               // pair D-1 -> slot D-1
    asm volatile("cp.async.commit_group;" ::: "memory");
    COLQ(0, 0);                           // c = cbeg: init only
    Aa = q1a; Ab = q1b; Ba = q0a; Bb = q0b;
    COLQ(0, 1);                           // c = cbeg+1
    if (cbeg + 1 >= sfirst)               // uniform (strip 0 stores out[0])
        store4(o + (size_t)cbeg * CC, badd(Aa, q2a), badd(Ab, q2b));
    Aa = badd(Ba, q1a); Ba = q0a;
    Ab = badd(Bb, q1b); Bb = q0b;

    // ---- main loop: pairs 1..27 (slot = p % D; always store) ----
#pragma unroll 4
    for (int p = 1; p < 28; ++p) {
        const int slot = p & (D - 1);
        asm volatile("cp.async.wait_group %0;" :: "n"(D - 2) : "memory");
        __syncwarp();

        // Refill FIRST: pair p+D-1 -> slot (p+D-1)%D == (slot+D-1)%D, the
        // slot read LAST iteration (all its reads ordered before this point
        // by the syncwarp above). Gets the loads in flight before compute.
        if (p + D - 1 < 28) {             // uniform
            const int rslot = (p + D - 1) & (D - 1);
            LOADPAIR(rslot, p + D - 1);
        }
        asm volatile("cp.async.commit_group;" ::: "memory");  // uniform counts

        const int c1 = cbeg + 2 * p;

        COLQ(slot, 0);                    // col c1: stores out[c1-1]
        store4(o + (size_t)(c1 - 1) * CC, badd(Aa, q2a), badd(Ab, q2b));
        Aa = badd(Ba, q1a); Ba = q0a;
        Ab = badd(Bb, q1b); Bb = q0b;

        COLQ(slot, 1);                    // col c1+1: stores out[c1]
        store4(o + (size_t)c1 * CC, badd(Aa, q2a), badd(Ab, q2b));
        Aa = badd(Ba, q1a); Ba = q0a;
        Ab = badd(Bb, q1b); Bb = q0b;
    }

    // ---- tail column cend (direct LDG). Band rows for MY output row are
    // derivable from L0/L1 with +-RS offsets (no new pointers):
    //  rr=0: rows (h-1, h, h+1) = (L0 clamped, L1, L1+RS)
    //  rr=1: rows (h-1, h, h+1) = (L0-RS, L0, L1 clamped)
    {
        const float* R0 = rr ? L0 - RS : L0;
        const float* R1 = rr ? L0      : L1;
        const float* R2 = rr ? L1      : L1 + RS;
        uint32_t t0a, t0b, t1a, t1b, t2a, t2b;
        carr(*reinterpret_cast<const uint4*>(R0 + (size_t)cend * CC), t0a, t0b);
        carr(*reinterpret_cast<const uint4*>(R1 + (size_t)cend * CC), t1a, t1b);
        carr(*reinterpret_cast<const uint4*>(R2 + (size_t)cend * CC), t2a, t2b);
        q1a = badd(badd(TAPP(t0a, kp[0][1][0]), TAPP(t1a, kp[1][1][0])), TAPP(t2a, kp[2][1][0]));
        q1b = badd(badd(TAPP(t0b, kp[0][1][1]), TAPP(t1b, kp[1][1][1])), TAPP(t2b, kp[2][1][1]));
        q2a = badd(badd(TAPP(t0a, kp[0][2][0]), TAPP(t1a, kp[1][2][0])), TAPP(t2a, kp[2][2][0]));
        q2b = badd(badd(TAPP(t0b, kp[0][2][1]), TAPP(t1b, kp[1][2][1])), TAPP(t2b, kp[2][2][1]));
        store4(o + (size_t)(cend - 1) * CC, badd(Aa, q2a), badd(Ab, q2b));
        Aa = badd(Ba, q1a);
        Ab = badd(Bb, q1b);
    }

    if (we == WW)  // right edge: out[111] = q0(110) + q1(111) = A
        store4(o + (size_t)(WW - 1) * CC, Aa, Ab);
}

extern "C" void kernel_launch(void* const* d_in, const int* in_sizes, int n_in,
                              void* d_out, int out_size) {
    const float* x = (const float*)d_in[0];
    const float* k = (const float*)d_in[1];
    float* out = (float*)d_out;
    dim3 grid(112, NN);   // 56 row-pairs x 2 strips
    bconv_kernel<<<grid, 128>>>(x, k, out);
}